// round 1
// baseline (speedup 1.0000x reference)
#include <cuda_runtime.h>
#include <math.h>

#define Nn 20000
#define Ff 32
#define Tt 12
#define Hh 64
#define Ee 320000
#define OUTD 12
#define KB 32

// ---------------- scratch (device globals; no allocation allowed) ----------
static __device__ float g_xt[(size_t)Tt * Nn * Ff];     // x transposed to (T,N,F)
static __device__ float g_deg[Nn];
static __device__ float g_dinv[Nn];
static __device__ float g_norm[Ee];
static __device__ int   g_cnt[Nn];
static __device__ int   g_cur[Nn];
static __device__ int   g_rowptr[Nn + 1];
static __device__ int   g_csrsrc[Ee];
static __device__ float g_csrnorm[Ee];
static __device__ float g_xw[(size_t)Nn * Hh];
static __device__ float g_gg[(size_t)Nn * Hh];
static __device__ float g_uu[(size_t)Nn * Hh];
static __device__ float g_rr[(size_t)Nn * Hh];
static __device__ float g_h0[(size_t)Nn * Hh];
static __device__ float g_h1[(size_t)Nn * Hh];
static __device__ float g_hseq[(size_t)Tt * Nn * Hh];

__device__ __forceinline__ float sigmoidf_(float x) { return 1.0f / (1.0f + __expf(-x)); }

// ---------------- preprocessing ----------------
__global__ void k_transpose(const float* __restrict__ x) {
    int idx = blockIdx.x * blockDim.x + threadIdx.x;
    if (idx >= Nn * Ff * Tt) return;
    int f = idx & (Ff - 1);
    int t = (idx / Ff) % Tt;
    int n = idx / (Ff * Tt);
    g_xt[(size_t)t * Nn * Ff + (size_t)n * Ff + f] = x[(size_t)n * Ff * Tt + (size_t)f * Tt + t];
}

__global__ void k_deg_hist(const int* __restrict__ ei, const float* __restrict__ ea) {
    int e = blockIdx.x * blockDim.x + threadIdx.x;
    if (e >= Ee) return;
    int d = ei[Ee + e];
    atomicAdd(&g_deg[d], ea[2 * e + 1]);
    atomicAdd(&g_cnt[d], 1);
}

__global__ void k_dinv() {
    int n = blockIdx.x * blockDim.x + threadIdx.x;
    if (n < Nn) g_dinv[n] = rsqrtf(g_deg[n] + 1.0f);   // +1 = self-loop weight
}

__global__ void k_norm(const int* __restrict__ ei, const float* __restrict__ ea) {
    int e = blockIdx.x * blockDim.x + threadIdx.x;
    if (e >= Ee) return;
    g_norm[e] = g_dinv[ei[e]] * ea[2 * e + 1] * g_dinv[ei[Ee + e]];
}

// single-block exclusive scan of g_cnt -> g_rowptr (N=20000, 20 chunks of 1024)
__global__ void k_scan() {
    __shared__ int sbuf[1024];
    __shared__ int s_carry;
    int tid = threadIdx.x;
    if (tid == 0) { s_carry = 0; g_rowptr[0] = 0; }
    __syncthreads();
    for (int base = 0; base < Nn; base += 1024) {
        int v = (base + tid < Nn) ? g_cnt[base + tid] : 0;
        sbuf[tid] = v;
        __syncthreads();
        for (int off = 1; off < 1024; off <<= 1) {
            int t2 = (tid >= off) ? sbuf[tid - off] : 0;
            __syncthreads();
            sbuf[tid] += t2;
            __syncthreads();
        }
        int incl = sbuf[tid] + s_carry;
        if (base + tid < Nn) g_rowptr[base + tid + 1] = incl;
        int total = sbuf[1023];
        __syncthreads();
        if (tid == 0) s_carry += total;
        __syncthreads();
    }
}

__global__ void k_fill(const int* __restrict__ ei) {
    int e = blockIdx.x * blockDim.x + threadIdx.x;
    if (e >= Ee) return;
    int d = ei[Ee + e];
    int pos = g_rowptr[d] + atomicAdd(&g_cur[d], 1);
    g_csrsrc[pos] = ei[e];
    g_csrnorm[pos] = g_norm[e];
}

// ---------------- GEMM: xw = A(N x KA) @ W(KA x 64) ----------------
__global__ __launch_bounds__(256) void k_gemm_xw(const float* __restrict__ A, int KA,
                                                 const float* __restrict__ W) {
    __shared__ float As[64][KB + 1];
    __shared__ float Ws[KB][Hh];
    int row0 = blockIdx.x * 64;
    int tid = threadIdx.x;
    int tx = tid & 15, ty = tid >> 4;
    float acc[4][4] = {};
    for (int k0 = 0; k0 < KA; k0 += KB) {
#pragma unroll
        for (int i = 0; i < 2; i++) {
            int f4 = tid + i * 256;
            int r = f4 >> 3, kf = (f4 & 7) << 2;
            int row = row0 + r;
            float4 v = make_float4(0.f, 0.f, 0.f, 0.f);
            if (row < Nn) v = *(const float4*)(A + (size_t)row * KA + k0 + kf);
            As[r][kf] = v.x; As[r][kf + 1] = v.y; As[r][kf + 2] = v.z; As[r][kf + 3] = v.w;
        }
#pragma unroll
        for (int i = 0; i < 2; i++) {
            int f4 = tid + i * 256;
            int k = f4 >> 4, jf = (f4 & 15) << 2;
            *(float4*)&Ws[k][jf] = *(const float4*)(W + (size_t)(k0 + k) * Hh + jf);
        }
        __syncthreads();
#pragma unroll
        for (int k = 0; k < KB; k++) {
            float a[4];
#pragma unroll
            for (int ii = 0; ii < 4; ii++) a[ii] = As[ty * 4 + ii][k];
            float4 w4 = *(const float4*)&Ws[k][tx * 4];
            float wv[4] = {w4.x, w4.y, w4.z, w4.w};
#pragma unroll
            for (int ii = 0; ii < 4; ii++)
#pragma unroll
                for (int jj = 0; jj < 4; jj++) acc[ii][jj] += a[ii] * wv[jj];
        }
        __syncthreads();
    }
#pragma unroll
    for (int ii = 0; ii < 4; ii++) {
        int row = row0 + ty * 4 + ii;
        if (row < Nn) {
            float4 o = make_float4(acc[ii][0], acc[ii][1], acc[ii][2], acc[ii][3]);
            *(float4*)(g_xw + (size_t)row * Hh + tx * 4) = o;
        }
    }
}

// ---------------- fused GCN aggregate + self-loop + bias + sigmoid -> g ----
__global__ void k_gcn_agg(const float* __restrict__ bg) {
    int n = blockIdx.x * (blockDim.x >> 5) + (threadIdx.x >> 5);
    if (n >= Nn) return;
    int lane = threadIdx.x & 31;
    int beg = g_rowptr[n], end = g_rowptr[n + 1];
    float a0 = 0.f, a1 = 0.f;
#pragma unroll 4
    for (int p = beg; p < end; p++) {
        int s = g_csrsrc[p];
        float nm = g_csrnorm[p];
        a0 += nm * g_xw[(size_t)s * Hh + lane];
        a1 += nm * g_xw[(size_t)s * Hh + lane + 32];
    }
    float dv = g_dinv[n];
    float dd = dv * dv;
    a0 += dd * g_xw[(size_t)n * Hh + lane] + bg[lane];
    a1 += dd * g_xw[(size_t)n * Hh + lane + 32] + bg[lane + 32];
    g_gg[(size_t)n * Hh + lane] = sigmoidf_(a0);
    g_gg[(size_t)n * Hh + lane + 32] = sigmoidf_(a1);
}

// ---------------- GEMM for u,r: [xi | g | h] @ {Wu,Wr} + bias, sigmoid -----
__global__ __launch_bounds__(256) void k_gemm_ur(
    const float* __restrict__ A1, int w1,
    const float* __restrict__ Wu, const float* __restrict__ bu,
    const float* __restrict__ Wr, const float* __restrict__ br,
    const float* __restrict__ hsrc) {
    __shared__ float As[64][KB + 1];
    __shared__ float Wus[KB][Hh];
    __shared__ float Wrs[KB][Hh];
    int row0 = blockIdx.x * 64;
    int tid = threadIdx.x;
    int tx = tid & 15, ty = tid >> 4;
    float aU[4][4] = {}, aR[4][4] = {};
    int KA = w1 + 2 * Hh;
    for (int k0 = 0; k0 < KA; k0 += KB) {
        const float* S; int sw, soff;
        if (k0 < w1)            { S = A1;   sw = w1; soff = k0; }
        else if (k0 < w1 + Hh)  { S = g_gg; sw = Hh; soff = k0 - w1; }
        else                    { S = hsrc; sw = Hh; soff = k0 - w1 - Hh; }
#pragma unroll
        for (int i = 0; i < 2; i++) {
            int f4 = tid + i * 256;
            int r = f4 >> 3, kf = (f4 & 7) << 2;
            int row = row0 + r;
            float4 v = make_float4(0.f, 0.f, 0.f, 0.f);
            if (row < Nn) v = *(const float4*)(S + (size_t)row * sw + soff + kf);
            As[r][kf] = v.x; As[r][kf + 1] = v.y; As[r][kf + 2] = v.z; As[r][kf + 3] = v.w;
        }
#pragma unroll
        for (int i = 0; i < 2; i++) {
            int f4 = tid + i * 256;
            int k = f4 >> 4, jf = (f4 & 15) << 2;
            *(float4*)&Wus[k][jf] = *(const float4*)(Wu + (size_t)(k0 + k) * Hh + jf);
            *(float4*)&Wrs[k][jf] = *(const float4*)(Wr + (size_t)(k0 + k) * Hh + jf);
        }
        __syncthreads();
#pragma unroll
        for (int k = 0; k < KB; k++) {
            float a[4];
#pragma unroll
            for (int ii = 0; ii < 4; ii++) a[ii] = As[ty * 4 + ii][k];
            float4 wu4 = *(const float4*)&Wus[k][tx * 4];
            float4 wr4 = *(const float4*)&Wrs[k][tx * 4];
            float wu[4] = {wu4.x, wu4.y, wu4.z, wu4.w};
            float wr[4] = {wr4.x, wr4.y, wr4.z, wr4.w};
#pragma unroll
            for (int ii = 0; ii < 4; ii++)
#pragma unroll
                for (int jj = 0; jj < 4; jj++) {
                    aU[ii][jj] += a[ii] * wu[jj];
                    aR[ii][jj] += a[ii] * wr[jj];
                }
        }
        __syncthreads();
    }
#pragma unroll
    for (int ii = 0; ii < 4; ii++) {
        int row = row0 + ty * 4 + ii;
        if (row >= Nn) continue;
#pragma unroll
        for (int jj = 0; jj < 4; jj++) {
            int col = tx * 4 + jj;
            g_uu[(size_t)row * Hh + col] = sigmoidf_(aU[ii][jj] + bu[col]);
            g_rr[(size_t)row * Hh + col] = sigmoidf_(aR[ii][jj] + br[col]);
        }
    }
}

// ---------------- GEMM for c + fused GRU state update ----------------------
__global__ __launch_bounds__(256) void k_gemm_c(
    const float* __restrict__ A1, int w1,
    const float* __restrict__ Wc, const float* __restrict__ bc,
    float* __restrict__ h, float* __restrict__ hseq) {
    __shared__ float As[64][KB + 1];
    __shared__ float Ws[KB][Hh];
    int row0 = blockIdx.x * 64;
    int tid = threadIdx.x;
    int tx = tid & 15, ty = tid >> 4;
    float acc[4][4] = {};
    int KA = w1 + 2 * Hh;
    for (int k0 = 0; k0 < KA; k0 += KB) {
        const float* S; int sw, soff; bool mul_r;
        if (k0 < w1)            { S = A1;   sw = w1; soff = k0;            mul_r = false; }
        else if (k0 < w1 + Hh)  { S = g_gg; sw = Hh; soff = k0 - w1;       mul_r = false; }
        else                    { S = h;    sw = Hh; soff = k0 - w1 - Hh;  mul_r = true;  }
#pragma unroll
        for (int i = 0; i < 2; i++) {
            int f4 = tid + i * 256;
            int r = f4 >> 3, kf = (f4 & 7) << 2;
            int row = row0 + r;
            float4 v = make_float4(0.f, 0.f, 0.f, 0.f);
            if (row < Nn) {
                v = *(const float4*)(S + (size_t)row * sw + soff + kf);
                if (mul_r) {
                    float4 rv = *(const float4*)(g_rr + (size_t)row * Hh + soff + kf);
                    v.x *= rv.x; v.y *= rv.y; v.z *= rv.z; v.w *= rv.w;
                }
            }
            As[r][kf] = v.x; As[r][kf + 1] = v.y; As[r][kf + 2] = v.z; As[r][kf + 3] = v.w;
        }
#pragma unroll
        for (int i = 0; i < 2; i++) {
            int f4 = tid + i * 256;
            int k = f4 >> 4, jf = (f4 & 15) << 2;
            *(float4*)&Ws[k][jf] = *(const float4*)(Wc + (size_t)(k0 + k) * Hh + jf);
        }
        __syncthreads();
#pragma unroll
        for (int k = 0; k < KB; k++) {
            float a[4];
#pragma unroll
            for (int ii = 0; ii < 4; ii++) a[ii] = As[ty * 4 + ii][k];
            float4 w4 = *(const float4*)&Ws[k][tx * 4];
            float wv[4] = {w4.x, w4.y, w4.z, w4.w};
#pragma unroll
            for (int ii = 0; ii < 4; ii++)
#pragma unroll
                for (int jj = 0; jj < 4; jj++) acc[ii][jj] += a[ii] * wv[jj];
        }
        __syncthreads();
    }
#pragma unroll
    for (int ii = 0; ii < 4; ii++) {
        int row = row0 + ty * 4 + ii;
        if (row >= Nn) continue;
#pragma unroll
        for (int jj = 0; jj < 4; jj++) {
            int col = tx * 4 + jj;
            size_t id = (size_t)row * Hh + col;
            float cv = tanhf(acc[ii][jj] + bc[col]);
            float uu = g_uu[id];
            float hn = uu * h[id] + (1.0f - uu) * cv;
            h[id] = hn;
            if (hseq) hseq[id] = hn;
        }
    }
}

// ---------------- fused attention + output head (1 warp per node) ----------
__global__ __launch_bounds__(32) void k_attn(
    const float* __restrict__ ipw, const float* __restrict__ ipb,
    const float* __restrict__ opw, const float* __restrict__ opb,
    const float* __restrict__ ow,  const float* __restrict__ ob,
    float* __restrict__ out) {
    __shared__ float sh_h[Tt * Hh];
    __shared__ float sh_q[Tt * Hh];   // reused as o after scores
    __shared__ float sh_k[Tt * Hh];
    __shared__ float sh_v[Tt * Hh];
    __shared__ float sh_sc[2 * Tt * Tt];
    __shared__ float sh_ob[Hh];
    __shared__ float sh_ha[Hh];
    int n = blockIdx.x;
    int lane = threadIdx.x;

    // load h_seq rows for this node
    for (int i = lane; i < (Tt * Hh) / 4; i += 32) {
        int off = i * 4;
        int t = off / Hh, j = off % Hh;
        *(float4*)&sh_h[off] = *(const float4*)&g_hseq[(size_t)t * Nn * Hh + (size_t)n * Hh + j];
    }
    __syncwarp();

    // qkv: lane owns rows i = lane + 32*m, m=0..5 ; acc over all 12 timesteps
    float acc[6][Tt];
#pragma unroll
    for (int m = 0; m < 6; m++)
#pragma unroll
        for (int t = 0; t < Tt; t++) acc[m][t] = 0.f;
    for (int j = 0; j < Hh; j++) {
        float w[6];
#pragma unroll
        for (int m = 0; m < 6; m++) w[m] = ipw[(size_t)(lane + 32 * m) * Hh + j];
#pragma unroll
        for (int t = 0; t < Tt; t++) {
            float hv = sh_h[t * Hh + j];
#pragma unroll
            for (int m = 0; m < 6; m++) acc[m][t] += w[m] * hv;
        }
    }
#pragma unroll
    for (int m = 0; m < 6; m++) {
        int i = lane + 32 * m;
        float b = ipb[i];
        float* buf = (m < 2) ? sh_q : ((m < 4) ? sh_k : sh_v);
        int col = i & 63;
#pragma unroll
        for (int t = 0; t < Tt; t++) buf[t * Hh + col] = acc[m][t] + b;
    }
    __syncwarp();

    // scores (2 heads x 12 x 12)
    for (int idx = lane; idx < 2 * Tt * Tt; idx += 32) {
        int hd = idx / (Tt * Tt);
        int r = idx % (Tt * Tt);
        int t = r / Tt, s = r % Tt;
        const float* qp = &sh_q[t * Hh + hd * 32];
        const float* kp = &sh_k[s * Hh + hd * 32];
        float a = 0.f;
#pragma unroll
        for (int d = 0; d < 32; d++) a += qp[d] * kp[d];
        sh_sc[idx] = a * 0.17677669529663687f;   // 1/sqrt(32)
    }
    __syncwarp();

    // softmax over s for each of 24 (head,t) rows
    if (lane < 2 * Tt) {
        float* row = &sh_sc[lane * Tt];
        float mx = row[0];
#pragma unroll
        for (int s = 1; s < Tt; s++) mx = fmaxf(mx, row[s]);
        float sum = 0.f;
#pragma unroll
        for (int s = 0; s < Tt; s++) { float e = __expf(row[s] - mx); row[s] = e; sum += e; }
        float inv = 1.0f / sum;
#pragma unroll
        for (int s = 0; s < Tt; s++) row[s] *= inv;
    }
    __syncwarp();

    // o = attn @ v  (into sh_q)
    for (int idx = lane; idx < Tt * Hh; idx += 32) {
        int t = idx / Hh, j = idx % Hh, hd = j >> 5;
        float a = 0.f;
#pragma unroll
        for (int s = 0; s < Tt; s++) a += sh_sc[hd * Tt * Tt + t * Tt + s] * sh_v[s * Hh + j];
        sh_q[idx] = a;
    }
    __syncwarp();

    // mean over t (out_proj is affine -> commute with mean)
    for (int j = lane; j < Hh; j += 32) {
        float s = 0.f;
#pragma unroll
        for (int t = 0; t < Tt; t++) s += sh_q[t * Hh + j];
        sh_ob[j] = s * (1.0f / 12.0f);
    }
    __syncwarp();

    // h_attn = obar @ out_proj_w.T + out_proj_b
    for (int i = lane; i < Hh; i += 32) {
        float a = opb[i];
#pragma unroll
        for (int j = 0; j < Hh; j++) a += opw[(size_t)i * Hh + j] * sh_ob[j];
        sh_ha[i] = a;
    }
    __syncwarp();

    // final head
    if (lane < OUTD) {
        float a = ob[lane];
#pragma unroll
        for (int i = 0; i < Hh; i++) a += sh_ha[i] * ow[(size_t)i * OUTD + lane];
        out[(size_t)n * OUTD + lane] = a;
    }
}

// ---------------- host ----------------
extern "C" void kernel_launch(void* const* d_in, const int* in_sizes, int n_in,
                              void* d_out, int out_size) {
    (void)in_sizes; (void)n_in; (void)out_size;
    const float* x   = (const float*)d_in[0];
    const int*   ei  = (const int*)d_in[1];
    const float* ea  = (const float*)d_in[2];
    const float* Wg0 = (const float*)d_in[3];
    const float* bg0 = (const float*)d_in[4];
    const float* Wu0 = (const float*)d_in[5];
    const float* bu0 = (const float*)d_in[6];
    const float* Wr0 = (const float*)d_in[7];
    const float* br0 = (const float*)d_in[8];
    const float* Wc0 = (const float*)d_in[9];
    const float* bc0 = (const float*)d_in[10];
    const float* Wg1 = (const float*)d_in[11];
    const float* bg1 = (const float*)d_in[12];
    const float* Wu1 = (const float*)d_in[13];
    const float* bu1 = (const float*)d_in[14];
    const float* Wr1 = (const float*)d_in[15];
    const float* br1 = (const float*)d_in[16];
    const float* Wc1 = (const float*)d_in[17];
    const float* bc1 = (const float*)d_in[18];
    const float* ipw = (const float*)d_in[19];
    const float* ipb = (const float*)d_in[20];
    const float* opw = (const float*)d_in[21];
    const float* opb = (const float*)d_in[22];
    const float* ow  = (const float*)d_in[23];
    const float* ob  = (const float*)d_in[24];
    float* out = (float*)d_out;

    void *p_deg, *p_cnt, *p_cur, *p_h0, *p_h1, *p_xt, *p_hseq;
    cudaGetSymbolAddress(&p_deg, g_deg);
    cudaGetSymbolAddress(&p_cnt, g_cnt);
    cudaGetSymbolAddress(&p_cur, g_cur);
    cudaGetSymbolAddress(&p_h0, g_h0);
    cudaGetSymbolAddress(&p_h1, g_h1);
    cudaGetSymbolAddress(&p_xt, g_xt);
    cudaGetSymbolAddress(&p_hseq, g_hseq);

    cudaMemsetAsync(p_deg, 0, Nn * sizeof(float), 0);
    cudaMemsetAsync(p_cnt, 0, Nn * sizeof(int), 0);
    cudaMemsetAsync(p_cur, 0, Nn * sizeof(int), 0);
    cudaMemsetAsync(p_h0, 0, (size_t)Nn * Hh * sizeof(float), 0);
    cudaMemsetAsync(p_h1, 0, (size_t)Nn * Hh * sizeof(float), 0);

    k_transpose<<<(Nn * Ff * Tt + 255) / 256, 256>>>(x);
    k_deg_hist<<<(Ee + 255) / 256, 256>>>(ei, ea);
    k_dinv<<<(Nn + 255) / 256, 256>>>();
    k_norm<<<(Ee + 255) / 256, 256>>>(ei, ea);
    k_scan<<<1, 1024>>>();
    k_fill<<<(Ee + 255) / 256, 256>>>(ei);

    const int GB = (Nn + 63) / 64;           // 313 row-tiles
    const int AGG_GRID = (Nn + 7) / 8;       // 8 warps/block

    float* h0 = (float*)p_h0;
    float* h1 = (float*)p_h1;

    for (int t = 0; t < Tt; t++) {
        // ---- layer 0: xi = x_t (N x F), state h0 ----
        const float* xi0 = (const float*)p_xt + (size_t)t * Nn * Ff;
        k_gemm_xw<<<GB, 256>>>(xi0, Ff, Wg0);
        k_gcn_agg<<<AGG_GRID, 256>>>(bg0);
        k_gemm_ur<<<GB, 256>>>(xi0, Ff, Wu0, bu0, Wr0, br0, h0);
        k_gemm_c<<<GB, 256>>>(xi0, Ff, Wc0, bc0, h0, (float*)0);

        // ---- layer 1: xi = h0 (N x H), state h1 ; record h1 into h_seq ----
        const float* xi1 = h0;
        k_gemm_xw<<<GB, 256>>>(xi1, Hh, Wg1);
        k_gcn_agg<<<AGG_GRID, 256>>>(bg1);
        k_gemm_ur<<<GB, 256>>>(xi1, Hh, Wu1, bu1, Wr1, br1, h1);
        k_gemm_c<<<GB, 256>>>(xi1, Hh, Wc1, bc1, h1, (float*)p_hseq + (size_t)t * Nn * Hh);
    }

    k_attn<<<Nn, 32>>>(ipw, ipb, opw, opb, ow, ob, out);
}

// round 3
// speedup vs baseline: 1.8138x; 1.8138x over previous
#include <cuda_runtime.h>
#include <math.h>

#define Nn 20000
#define Ff 32
#define Tt 12
#define Hh 64
#define Ee 320000
#define OUTD 12
#define KB 32
#define TN (Tt * Nn)

// ---------------- scratch (device globals; no runtime allocation) ----------
static __device__ float g_xt[(size_t)TN * Ff];        // x transposed to (T,N,F)
static __device__ float g_deg[Nn];
static __device__ float g_dinv[Nn];
static __device__ float g_norm[Ee];
static __device__ int   g_cnt[Nn];
static __device__ int   g_cur[Nn];
static __device__ int   g_rowptr[Nn + 1];
static __device__ int   g_csrsrc[Ee];
static __device__ float g_csrnorm[Ee];
static __device__ float g_xw0all[(size_t)TN * Hh];    // x_t @ Wg0 for all t
static __device__ float g_g0all[(size_t)TN * Hh];     // sigmoid(agg) for all t (layer0)
static __device__ float g_p0all[(size_t)TN * 192];    // [x|g] @ (Wu|Wr|Wc)[0:96] + bias
static __device__ float g_xw[(size_t)Nn * Hh];        // layer1 xw
static __device__ float g_gg[(size_t)Nn * Hh];        // layer1 g
static __device__ float g_h0[(size_t)Nn * Hh];
static __device__ float g_h1[(size_t)Nn * Hh];
static __device__ float g_hseq[(size_t)TN * Hh];
static __device__ float g_ipwT[192 * Hh];             // transposed in_proj_w [j][i]
static __device__ float g_opwT[Hh * Hh];              // transposed out_proj_w [j][i]

__device__ __forceinline__ float sigmoidf_(float x) { return 1.0f / (1.0f + __expf(-x)); }

// ---------------- preprocessing ----------------
__global__ void k_transpose(const float* __restrict__ x) {
    int idx = blockIdx.x * blockDim.x + threadIdx.x;
    if (idx >= Nn * Ff * Tt) return;
    int f = idx & (Ff - 1);
    int t = (idx / Ff) % Tt;
    int n = idx / (Ff * Tt);
    g_xt[(size_t)t * Nn * Ff + (size_t)n * Ff + f] = x[(size_t)n * Ff * Tt + (size_t)f * Tt + t];
}

__global__ void k_trW(const float* __restrict__ ipw, const float* __restrict__ opw) {
    int i = blockIdx.x * blockDim.x + threadIdx.x;
    if (i < 192 * Hh) { int r = i / Hh, c = i % Hh; g_ipwT[c * 192 + r] = ipw[i]; }
    if (i < Hh * Hh)  { int r = i / Hh, c = i % Hh; g_opwT[c * Hh + r] = opw[i]; }
}

__global__ void k_deg_hist(const int* __restrict__ ei, const float* __restrict__ ea) {
    int e = blockIdx.x * blockDim.x + threadIdx.x;
    if (e >= Ee) return;
    int d = ei[Ee + e];
    atomicAdd(&g_deg[d], ea[2 * e + 1]);
    atomicAdd(&g_cnt[d], 1);
}

__global__ void k_dinv() {
    int n = blockIdx.x * blockDim.x + threadIdx.x;
    if (n < Nn) g_dinv[n] = rsqrtf(g_deg[n] + 1.0f);   // +1 = self-loop weight
}

__global__ void k_norm(const int* __restrict__ ei, const float* __restrict__ ea) {
    int e = blockIdx.x * blockDim.x + threadIdx.x;
    if (e >= Ee) return;
    g_norm[e] = g_dinv[ei[e]] * ea[2 * e + 1] * g_dinv[ei[Ee + e]];
}

// single-block exclusive scan of g_cnt -> g_rowptr
__global__ void k_scan() {
    __shared__ int sbuf[1024];
    __shared__ int s_carry;
    int tid = threadIdx.x;
    if (tid == 0) { s_carry = 0; g_rowptr[0] = 0; }
    __syncthreads();
    for (int base = 0; base < Nn; base += 1024) {
        int v = (base + tid < Nn) ? g_cnt[base + tid] : 0;
        sbuf[tid] = v;
        __syncthreads();
        for (int off = 1; off < 1024; off <<= 1) {
            int t2 = (tid >= off) ? sbuf[tid - off] : 0;
            __syncthreads();
            sbuf[tid] += t2;
            __syncthreads();
        }
        int incl = sbuf[tid] + s_carry;
        if (base + tid < Nn) g_rowptr[base + tid + 1] = incl;
        int total = sbuf[1023];
        __syncthreads();
        if (tid == 0) s_carry += total;
        __syncthreads();
    }
}

__global__ void k_fill(const int* __restrict__ ei) {
    int e = blockIdx.x * blockDim.x + threadIdx.x;
    if (e >= Ee) return;
    int d = ei[Ee + e];
    int pos = g_rowptr[d] + atomicAdd(&g_cur[d], 1);
    g_csrsrc[pos] = ei[e];
    g_csrnorm[pos] = g_norm[e];
}

// ---------------- generic GEMM: out = A(M x KA) @ W(KA x 64) ----------------
__global__ __launch_bounds__(256) void k_gemm_xw(const float* __restrict__ A, int KA, int M,
                                                 const float* __restrict__ W,
                                                 float* __restrict__ out) {
    __shared__ float As[64][KB + 1];
    __shared__ float Ws[KB][Hh];
    int row0 = blockIdx.x * 64;
    int tid = threadIdx.x;
    int tx = tid & 15, ty = tid >> 4;
    float acc[4][4] = {};
    for (int k0 = 0; k0 < KA; k0 += KB) {
#pragma unroll
        for (int i = 0; i < 2; i++) {
            int f4 = tid + i * 256;
            int r = f4 >> 3, kf = (f4 & 7) << 2;
            int row = row0 + r;
            float4 v = make_float4(0.f, 0.f, 0.f, 0.f);
            if (row < M) v = *(const float4*)(A + (size_t)row * KA + k0 + kf);
            As[r][kf] = v.x; As[r][kf + 1] = v.y; As[r][kf + 2] = v.z; As[r][kf + 3] = v.w;
        }
#pragma unroll
        for (int i = 0; i < 2; i++) {
            int f4 = tid + i * 256;
            int k = f4 >> 4, jf = (f4 & 15) << 2;
            *(float4*)&Ws[k][jf] = *(const float4*)(W + (size_t)(k0 + k) * Hh + jf);
        }
        __syncthreads();
#pragma unroll
        for (int k = 0; k < KB; k++) {
            float a[4];
#pragma unroll
            for (int ii = 0; ii < 4; ii++) a[ii] = As[ty * 4 + ii][k];
            float4 w4 = *(const float4*)&Ws[k][tx * 4];
            float wv[4] = {w4.x, w4.y, w4.z, w4.w};
#pragma unroll
            for (int ii = 0; ii < 4; ii++)
#pragma unroll
                for (int jj = 0; jj < 4; jj++) acc[ii][jj] += a[ii] * wv[jj];
        }
        __syncthreads();
    }
#pragma unroll
    for (int ii = 0; ii < 4; ii++) {
        int row = row0 + ty * 4 + ii;
        if (row < M) {
            float4 o = make_float4(acc[ii][0], acc[ii][1], acc[ii][2], acc[ii][3]);
            *(float4*)(out + (size_t)row * Hh + tx * 4) = o;
        }
    }
}

// ---------------- big precompute GEMM: p0 = [x_t|g0_t] @ W[0:96] + b -------
// grid.y selects output block: 0 -> Wu, 1 -> Wr, 2 -> Wc
__global__ __launch_bounds__(256) void k_pre0(
    const float* __restrict__ Wu, const float* __restrict__ bu,
    const float* __restrict__ Wr, const float* __restrict__ br,
    const float* __restrict__ Wc, const float* __restrict__ bc) {
    __shared__ float As[64][KB + 1];
    __shared__ float Ws[KB][Hh];
    int cb = blockIdx.y;
    const float* W = (cb == 0) ? Wu : (cb == 1) ? Wr : Wc;
    const float* b = (cb == 0) ? bu : (cb == 1) ? br : bc;
    int row0 = blockIdx.x * 64;
    int tid = threadIdx.x;
    int tx = tid & 15, ty = tid >> 4;
    float acc[4][4] = {};
    for (int k0 = 0; k0 < 96; k0 += KB) {
        const float* S; int sw, soff;
        if (k0 < Ff) { S = g_xt;    sw = Ff; soff = k0; }
        else         { S = g_g0all; sw = Hh; soff = k0 - Ff; }
#pragma unroll
        for (int i = 0; i < 2; i++) {
            int f4 = tid + i * 256;
            int r = f4 >> 3, kf = (f4 & 7) << 2;
            int row = row0 + r;
            float4 v = *(const float4*)(S + (size_t)row * sw + soff + kf);
            As[r][kf] = v.x; As[r][kf + 1] = v.y; As[r][kf + 2] = v.z; As[r][kf + 3] = v.w;
        }
#pragma unroll
        for (int i = 0; i < 2; i++) {
            int f4 = tid + i * 256;
            int k = f4 >> 4, jf = (f4 & 15) << 2;
            *(float4*)&Ws[k][jf] = *(const float4*)(W + (size_t)(k0 + k) * Hh + jf);
        }
        __syncthreads();
#pragma unroll
        for (int k = 0; k < KB; k++) {
            float a[4];
#pragma unroll
            for (int ii = 0; ii < 4; ii++) a[ii] = As[ty * 4 + ii][k];
            float4 w4 = *(const float4*)&Ws[k][tx * 4];
            float wv[4] = {w4.x, w4.y, w4.z, w4.w};
#pragma unroll
            for (int ii = 0; ii < 4; ii++)
#pragma unroll
                for (int jj = 0; jj < 4; jj++) acc[ii][jj] += a[ii] * wv[jj];
        }
        __syncthreads();
    }
#pragma unroll
    for (int ii = 0; ii < 4; ii++) {
        int row = row0 + ty * 4 + ii;
        int col = tx * 4;
        float4 o = make_float4(acc[ii][0] + b[col], acc[ii][1] + b[col + 1],
                               acc[ii][2] + b[col + 2], acc[ii][3] + b[col + 3]);
        *(float4*)(g_p0all + (size_t)row * 192 + cb * Hh + col) = o;
    }
}

// ---------------- GCN aggregate for ALL timesteps (layer0) -----------------
__global__ void k_agg_all(const float* __restrict__ bg) {
    int gw = blockIdx.x * (blockDim.x >> 5) + (threadIdx.x >> 5);
    if (gw >= TN) return;
    int t = gw / Nn, n = gw - t * Nn;
    int lane = threadIdx.x & 31;
    const float* xw = g_xw0all + (size_t)t * Nn * Hh;
    int beg = g_rowptr[n], end = g_rowptr[n + 1];
    float a0 = 0.f, a1 = 0.f;
#pragma unroll 4
    for (int p = beg; p < end; p++) {
        int s = g_csrsrc[p];
        float nm = g_csrnorm[p];
        a0 += nm * xw[(size_t)s * Hh + lane];
        a1 += nm * xw[(size_t)s * Hh + lane + 32];
    }
    float dv = g_dinv[n];
    float dd = dv * dv;
    a0 += dd * xw[(size_t)n * Hh + lane] + bg[lane];
    a1 += dd * xw[(size_t)n * Hh + lane + 32] + bg[lane + 32];
    g_g0all[(size_t)gw * Hh + lane] = sigmoidf_(a0);
    g_g0all[(size_t)gw * Hh + lane + 32] = sigmoidf_(a1);
}

// ---------------- per-step GCN aggregate (layer1) ---------------------------
__global__ void k_gcn_agg(const float* __restrict__ bg) {
    int n = blockIdx.x * (blockDim.x >> 5) + (threadIdx.x >> 5);
    if (n >= Nn) return;
    int lane = threadIdx.x & 31;
    int beg = g_rowptr[n], end = g_rowptr[n + 1];
    float a0 = 0.f, a1 = 0.f;
#pragma unroll 4
    for (int p = beg; p < end; p++) {
        int s = g_csrsrc[p];
        float nm = g_csrnorm[p];
        a0 += nm * g_xw[(size_t)s * Hh + lane];
        a1 += nm * g_xw[(size_t)s * Hh + lane + 32];
    }
    float dv = g_dinv[n];
    float dd = dv * dv;
    a0 += dd * g_xw[(size_t)n * Hh + lane] + bg[lane];
    a1 += dd * g_xw[(size_t)n * Hh + lane + 32] + bg[lane + 32];
    g_gg[(size_t)n * Hh + lane] = sigmoidf_(a0);
    g_gg[(size_t)n * Hh + lane + 32] = sigmoidf_(a1);
}

// ---------------- layer0 fused u,r,c + GRU update (K=64 over h) -------------
__global__ __launch_bounds__(256) void k_urc0(
    const float* __restrict__ Wu96, const float* __restrict__ Wr96,
    const float* __restrict__ Wc96, const float* __restrict__ p0,
    float* __restrict__ h) {
    __shared__ float As[64][KB + 1];
    __shared__ float Wcs[KB][Hh];
    __shared__ float WuRs[2 * KB * Hh];           // pass1: Wu,Wr ; then Rs[64][64]
    float* Wus = WuRs;
    float* Wrs = WuRs + KB * Hh;
    float* Rs  = WuRs;
    int row0 = blockIdx.x * 64;
    int tid = threadIdx.x;
    int tx = tid & 15, ty = tid >> 4;
    float aU[4][4], aR[4][4], aC[4][4];
#pragma unroll
    for (int ii = 0; ii < 4; ii++) {
        int row = row0 + ty * 4 + ii;
        float4 u4 = make_float4(0,0,0,0), r4 = u4, c4 = u4;
        if (row < Nn) {
            u4 = *(const float4*)(p0 + (size_t)row * 192 + tx * 4);
            r4 = *(const float4*)(p0 + (size_t)row * 192 + 64 + tx * 4);
            c4 = *(const float4*)(p0 + (size_t)row * 192 + 128 + tx * 4);
        }
        aU[ii][0]=u4.x; aU[ii][1]=u4.y; aU[ii][2]=u4.z; aU[ii][3]=u4.w;
        aR[ii][0]=r4.x; aR[ii][1]=r4.y; aR[ii][2]=r4.z; aR[ii][3]=r4.w;
        aC[ii][0]=c4.x; aC[ii][1]=c4.y; aC[ii][2]=c4.z; aC[ii][3]=c4.w;
    }
    // pass1: K=64 over h with Wu[96:],Wr[96:]
    for (int k0 = 0; k0 < Hh; k0 += KB) {
#pragma unroll
        for (int i = 0; i < 2; i++) {
            int f4 = tid + i * 256;
            int r = f4 >> 3, kf = (f4 & 7) << 2;
            int row = row0 + r;
            float4 v = make_float4(0,0,0,0);
            if (row < Nn) v = *(const float4*)(h + (size_t)row * Hh + k0 + kf);
            As[r][kf]=v.x; As[r][kf+1]=v.y; As[r][kf+2]=v.z; As[r][kf+3]=v.w;
        }
#pragma unroll
        for (int i = 0; i < 2; i++) {
            int f4 = tid + i * 256;
            int k = f4 >> 4, jf = (f4 & 15) << 2;
            *(float4*)&Wus[k * Hh + jf] = *(const float4*)(Wu96 + (size_t)(k0 + k) * Hh + jf);
            *(float4*)&Wrs[k * Hh + jf] = *(const float4*)(Wr96 + (size_t)(k0 + k) * Hh + jf);
        }
        __syncthreads();
#pragma unroll
        for (int k = 0; k < KB; k++) {
            float a[4];
#pragma unroll
            for (int ii = 0; ii < 4; ii++) a[ii] = As[ty * 4 + ii][k];
            float4 wu4 = *(const float4*)&Wus[k * Hh + tx * 4];
            float4 wr4 = *(const float4*)&Wrs[k * Hh + tx * 4];
            float wu[4]={wu4.x,wu4.y,wu4.z,wu4.w}, wr[4]={wr4.x,wr4.y,wr4.z,wr4.w};
#pragma unroll
            for (int ii = 0; ii < 4; ii++)
#pragma unroll
                for (int jj = 0; jj < 4; jj++) {
                    aU[ii][jj] += a[ii] * wu[jj];
                    aR[ii][jj] += a[ii] * wr[jj];
                }
        }
        __syncthreads();
    }
    // sigmoid; r -> smem
    float uV[4][4];
#pragma unroll
    for (int ii = 0; ii < 4; ii++)
#pragma unroll
        for (int jj = 0; jj < 4; jj++) {
            uV[ii][jj] = sigmoidf_(aU[ii][jj]);
            Rs[(ty * 4 + ii) * Hh + tx * 4 + jj] = sigmoidf_(aR[ii][jj]);
        }
    __syncthreads();
    // pass2: aC += (r*h) @ Wc[96:]
    for (int k0 = 0; k0 < Hh; k0 += KB) {
#pragma unroll
        for (int i = 0; i < 2; i++) {
            int f4 = tid + i * 256;
            int r = f4 >> 3, kf = (f4 & 7) << 2;
            int row = row0 + r;
            float4 v = make_float4(0,0,0,0);
            if (row < Nn) v = *(const float4*)(h + (size_t)row * Hh + k0 + kf);
            As[r][kf]   = v.x * Rs[r * Hh + k0 + kf];
            As[r][kf+1] = v.y * Rs[r * Hh + k0 + kf + 1];
            As[r][kf+2] = v.z * Rs[r * Hh + k0 + kf + 2];
            As[r][kf+3] = v.w * Rs[r * Hh + k0 + kf + 3];
        }
#pragma unroll
        for (int i = 0; i < 2; i++) {
            int f4 = tid + i * 256;
            int k = f4 >> 4, jf = (f4 & 15) << 2;
            *(float4*)&Wcs[k][jf] = *(const float4*)(Wc96 + (size_t)(k0 + k) * Hh + jf);
        }
        __syncthreads();
#pragma unroll
        for (int k = 0; k < KB; k++) {
            float a[4];
#pragma unroll
            for (int ii = 0; ii < 4; ii++) a[ii] = As[ty * 4 + ii][k];
            float4 w4 = *(const float4*)&Wcs[k][tx * 4];
            float wv[4]={w4.x,w4.y,w4.z,w4.w};
#pragma unroll
            for (int ii = 0; ii < 4; ii++)
#pragma unroll
                for (int jj = 0; jj < 4; jj++) aC[ii][jj] += a[ii] * wv[jj];
        }
        __syncthreads();
    }
    // update
#pragma unroll
    for (int ii = 0; ii < 4; ii++) {
        int row = row0 + ty * 4 + ii;
        if (row >= Nn) continue;
        float4 h4 = *(const float4*)(h + (size_t)row * Hh + tx * 4);
        float hv[4] = {h4.x, h4.y, h4.z, h4.w};
        float4 o;
        float* op = (float*)&o;
#pragma unroll
        for (int jj = 0; jj < 4; jj++) {
            float cv = tanhf(aC[ii][jj]);
            op[jj] = uV[ii][jj] * hv[jj] + (1.0f - uV[ii][jj]) * cv;
        }
        *(float4*)(h + (size_t)row * Hh + tx * 4) = o;
    }
}

// ---------------- layer1 fused u,r,c + GRU update (K=192) -------------------
__global__ __launch_bounds__(256) void k_urc1(
    const float* __restrict__ h0,
    const float* __restrict__ Wu, const float* __restrict__ bu,
    const float* __restrict__ Wr, const float* __restrict__ br,
    const float* __restrict__ Wc, const float* __restrict__ bc,
    float* __restrict__ h, float* __restrict__ hseq) {
    __shared__ float As[64][KB + 1];
    __shared__ float Wcs[KB][Hh];
    __shared__ float WuRs[2 * KB * Hh];
    float* Wus = WuRs;
    float* Wrs = WuRs + KB * Hh;
    float* Rs  = WuRs;
    int row0 = blockIdx.x * 64;
    int tid = threadIdx.x;
    int tx = tid & 15, ty = tid >> 4;
    float aU[4][4] = {}, aR[4][4] = {}, aC[4][4] = {};
    // pass1: K=192 over [h0 | g | h]; aC only over first 128
    for (int k0 = 0; k0 < 192; k0 += KB) {
        const float* S; int soff;
        if (k0 < Hh)            { S = h0;   soff = k0; }
        else if (k0 < 2 * Hh)   { S = g_gg; soff = k0 - Hh; }
        else                    { S = h;    soff = k0 - 2 * Hh; }
        bool do_c = (k0 < 2 * Hh);
#pragma unroll
        for (int i = 0; i < 2; i++) {
            int f4 = tid + i * 256;
            int r = f4 >> 3, kf = (f4 & 7) << 2;
            int row = row0 + r;
            float4 v = make_float4(0,0,0,0);
            if (row < Nn) v = *(const float4*)(S + (size_t)row * Hh + soff + kf);
            As[r][kf]=v.x; As[r][kf+1]=v.y; As[r][kf+2]=v.z; As[r][kf+3]=v.w;
        }
#pragma unroll
        for (int i = 0; i < 2; i++) {
            int f4 = tid + i * 256;
            int k = f4 >> 4, jf = (f4 & 15) << 2;
            *(float4*)&Wus[k * Hh + jf] = *(const float4*)(Wu + (size_t)(k0 + k) * Hh + jf);
            *(float4*)&Wrs[k * Hh + jf] = *(const float4*)(Wr + (size_t)(k0 + k) * Hh + jf);
            if (do_c)
                *(float4*)&Wcs[k][jf] = *(const float4*)(Wc + (size_t)(k0 + k) * Hh + jf);
        }
        __syncthreads();
        if (do_c) {
#pragma unroll
            for (int k = 0; k < KB; k++) {
                float a[4];
#pragma unroll
                for (int ii = 0; ii < 4; ii++) a[ii] = As[ty * 4 + ii][k];
                float4 wu4 = *(const float4*)&Wus[k * Hh + tx * 4];
                float4 wr4 = *(const float4*)&Wrs[k * Hh + tx * 4];
                float4 wc4 = *(const float4*)&Wcs[k][tx * 4];
                float wu[4]={wu4.x,wu4.y,wu4.z,wu4.w};
                float wr[4]={wr4.x,wr4.y,wr4.z,wr4.w};
                float wc[4]={wc4.x,wc4.y,wc4.z,wc4.w};
#pragma unroll
                for (int ii = 0; ii < 4; ii++)
#pragma unroll
                    for (int jj = 0; jj < 4; jj++) {
                        aU[ii][jj] += a[ii] * wu[jj];
                        aR[ii][jj] += a[ii] * wr[jj];
                        aC[ii][jj] += a[ii] * wc[jj];
                    }
            }
        } else {
#pragma unroll
            for (int k = 0; k < KB; k++) {
                float a[4];
#pragma unroll
                for (int ii = 0; ii < 4; ii++) a[ii] = As[ty * 4 + ii][k];
                float4 wu4 = *(const float4*)&Wus[k * Hh + tx * 4];
                float4 wr4 = *(const float4*)&Wrs[k * Hh + tx * 4];
                float wu[4]={wu4.x,wu4.y,wu4.z,wu4.w};
                float wr[4]={wr4.x,wr4.y,wr4.z,wr4.w};
#pragma unroll
                for (int ii = 0; ii < 4; ii++)
#pragma unroll
                    for (int jj = 0; jj < 4; jj++) {
                        aU[ii][jj] += a[ii] * wu[jj];
                        aR[ii][jj] += a[ii] * wr[jj];
                    }
            }
        }
        __syncthreads();
    }
    // sigmoid with bias; r -> smem
    float uV[4][4];
#pragma unroll
    for (int ii = 0; ii < 4; ii++)
#pragma unroll
        for (int jj = 0; jj < 4; jj++) {
            int col = tx * 4 + jj;
            uV[ii][jj] = sigmoidf_(aU[ii][jj] + bu[col]);
            Rs[(ty * 4 + ii) * Hh + col] = sigmoidf_(aR[ii][jj] + br[col]);
        }
    __syncthreads();
    // pass2: aC += (r*h) @ Wc[128:]
    for (int k0 = 0; k0 < Hh; k0 += KB) {
#pragma unroll
        for (int i = 0; i < 2; i++) {
            int f4 = tid + i * 256;
            int r = f4 >> 3, kf = (f4 & 7) << 2;
            int row = row0 + r;
            float4 v = make_float4(0,0,0,0);
            if (row < Nn) v = *(const float4*)(h + (size_t)row * Hh + k0 + kf);
            As[r][kf]   = v.x * Rs[r * Hh + k0 + kf];
            As[r][kf+1] = v.y * Rs[r * Hh + k0 + kf + 1];
            As[r][kf+2] = v.z * Rs[r * Hh + k0 + kf + 2];
            As[r][kf+3] = v.w * Rs[r * Hh + k0 + kf + 3];
        }
#pragma unroll
        for (int i = 0; i < 2; i++) {
            int f4 = tid + i * 256;
            int k = f4 >> 4, jf = (f4 & 15) << 2;
            *(float4*)&Wcs[k][jf] = *(const float4*)(Wc + (size_t)(128 + k0 + k) * Hh + jf);
        }
        __syncthreads();
#pragma unroll
        for (int k = 0; k < KB; k++) {
            float a[4];
#pragma unroll
            for (int ii = 0; ii < 4; ii++) a[ii] = As[ty * 4 + ii][k];
            float4 w4 = *(const float4*)&Wcs[k][tx * 4];
            float wv[4]={w4.x,w4.y,w4.z,w4.w};
#pragma unroll
            for (int ii = 0; ii < 4; ii++)
#pragma unroll
                for (int jj = 0; jj < 4; jj++) aC[ii][jj] += a[ii] * wv[jj];
        }
        __syncthreads();
    }
    // update + hseq
#pragma unroll
    for (int ii = 0; ii < 4; ii++) {
        int row = row0 + ty * 4 + ii;
        if (row >= Nn) continue;
        float4 h4 = *(const float4*)(h + (size_t)row * Hh + tx * 4);
        float hv[4] = {h4.x, h4.y, h4.z, h4.w};
        float4 o;
        float* op = (float*)&o;
#pragma unroll
        for (int jj = 0; jj < 4; jj++) {
            int col = tx * 4 + jj;
            float cv = tanhf(aC[ii][jj] + bc[col]);
            op[jj] = uV[ii][jj] * hv[jj] + (1.0f - uV[ii][jj]) * cv;
        }
        *(float4*)(h + (size_t)row * Hh + tx * 4) = o;
        *(float4*)(hseq + (size_t)row * Hh + tx * 4) = o;
    }
}

// ---------------- fused attention + output head (1 warp per node) ----------
__global__ __launch_bounds__(32) void k_attn(
    const float* __restrict__ ipb,
    const float* __restrict__ opb,
    const float* __restrict__ ow,  const float* __restrict__ ob,
    float* __restrict__ out) {
    __shared__ float sh_h[Tt * Hh];
    __shared__ float sh_q[Tt * Hh];
    __shared__ float sh_k[Tt * Hh];
    __shared__ float sh_v[Tt * Hh];
    __shared__ float sh_sc[2 * Tt * Tt];
    __shared__ float sh_ob[Hh];
    __shared__ float sh_ha[Hh];
    int n = blockIdx.x;
    int lane = threadIdx.x;

    for (int i = lane; i < (Tt * Hh) / 4; i += 32) {
        int off = i * 4;
        int t = off / Hh, j = off % Hh;
        *(float4*)&sh_h[off] = *(const float4*)&g_hseq[(size_t)t * Nn * Hh + (size_t)n * Hh + j];
    }
    __syncwarp();

    // qkv with transposed weights (coalesced loads)
    float acc[6][Tt];
#pragma unroll
    for (int m = 0; m < 6; m++)
#pragma unroll
        for (int t = 0; t < Tt; t++) acc[m][t] = 0.f;
    for (int j = 0; j < Hh; j++) {
        float w[6];
#pragma unroll
        for (int m = 0; m < 6; m++) w[m] = g_ipwT[j * 192 + lane + 32 * m];
#pragma unroll
        for (int t = 0; t < Tt; t++) {
            float hv = sh_h[t * Hh + j];
#pragma unroll
            for (int m = 0; m < 6; m++) acc[m][t] += w[m] * hv;
        }
    }
#pragma unroll
    for (int m = 0; m < 6; m++) {
        int i = lane + 32 * m;
        float b = ipb[i];
        float* buf = (m < 2) ? sh_q : ((m < 4) ? sh_k : sh_v);
        int col = i & 63;
#pragma unroll
        for (int t = 0; t < Tt; t++) buf[t * Hh + col] = acc[m][t] + b;
    }
    __syncwarp();

    for (int idx = lane; idx < 2 * Tt * Tt; idx += 32) {
        int hd = idx / (Tt * Tt);
        int r = idx % (Tt * Tt);
        int t = r / Tt, s = r % Tt;
        const float* qp = &sh_q[t * Hh + hd * 32];
        const float* kp = &sh_k[s * Hh + hd * 32];
        float a = 0.f;
#pragma unroll
        for (int d = 0; d < 32; d++) a += qp[d] * kp[d];
        sh_sc[idx] = a * 0.17677669529663687f;
    }
    __syncwarp();

    if (lane < 2 * Tt) {
        float* row = &sh_sc[lane * Tt];
        float mx = row[0];
#pragma unroll
        for (int s = 1; s < Tt; s++) mx = fmaxf(mx, row[s]);
        float sum = 0.f;
#pragma unroll
        for (int s = 0; s < Tt; s++) { float e = __expf(row[s] - mx); row[s] = e; sum += e; }
        float inv = 1.0f / sum;
#pragma unroll
        for (int s = 0; s < Tt; s++) row[s] *= inv;
    }
    __syncwarp();

    for (int idx = lane; idx < Tt * Hh; idx += 32) {
        int t = idx / Hh, j = idx % Hh, hd = j >> 5;
        float a = 0.f;
#pragma unroll
        for (int s = 0; s < Tt; s++) a += sh_sc[hd * Tt * Tt + t * Tt + s] * sh_v[s * Hh + j];
        sh_q[idx] = a;
    }
    __syncwarp();

    for (int j = lane; j < Hh; j += 32) {
        float s = 0.f;
#pragma unroll
        for (int t = 0; t < Tt; t++) s += sh_q[t * Hh + j];
        sh_ob[j] = s * (1.0f / 12.0f);
    }
    __syncwarp();

    // h_attn = obar @ opw.T (transposed weights -> coalesced)
    for (int m = 0; m < 2; m++) {
        int i = lane + 32 * m;
        float a = opb[i];
#pragma unroll
        for (int j = 0; j < Hh; j++) a += g_opwT[j * Hh + i] * sh_ob[j];
        sh_ha[i] = a;
    }
    __syncwarp();

    if (lane < OUTD) {
        float a = ob[lane];
#pragma unroll
        for (int i = 0; i < Hh; i++) a += sh_ha[i] * ow[(size_t)i * OUTD + lane];
        out[(size_t)n * OUTD + lane] = a;
    }
}

// ---------------- host ----------------
extern "C" void kernel_launch(void* const* d_in, const int* in_sizes, int n_in,
                              void* d_out, int out_size) {
    (void)in_sizes; (void)n_in; (void)out_size;
    const float* x   = (const float*)d_in[0];
    const int*   ei  = (const int*)d_in[1];
    const float* ea  = (const float*)d_in[2];
    const float* Wg0 = (const float*)d_in[3];
    const float* bg0 = (const float*)d_in[4];
    const float* Wu0 = (const float*)d_in[5];
    const float* bu0 = (const float*)d_in[6];
    const float* Wr0 = (const float*)d_in[7];
    const float* br0 = (const float*)d_in[8];
    const float* Wc0 = (const float*)d_in[9];
    const float* bc0 = (const float*)d_in[10];
    const float* Wg1 = (const float*)d_in[11];
    const float* bg1 = (const float*)d_in[12];
    const float* Wu1 = (const float*)d_in[13];
    const float* bu1 = (const float*)d_in[14];
    const float* Wr1 = (const float*)d_in[15];
    const float* br1 = (const float*)d_in[16];
    const float* Wc1 = (const float*)d_in[17];
    const float* bc1 = (const float*)d_in[18];
    const float* ipw = (const float*)d_in[19];
    const float* ipb = (const float*)d_in[20];
    const float* opw = (const float*)d_in[21];
    const float* opb = (const float*)d_in[22];
    const float* ow  = (const float*)d_in[23];
    const float* ob  = (const float*)d_in[24];
    float* out = (float*)d_out;

    void *p_deg, *p_cnt, *p_cur, *p_h0, *p_h1, *p_xt, *p_hseq, *p_xw0all, *p_p0all, *p_xw;
    cudaGetSymbolAddress(&p_deg, g_deg);
    cudaGetSymbolAddress(&p_cnt, g_cnt);
    cudaGetSymbolAddress(&p_cur, g_cur);
    cudaGetSymbolAddress(&p_h0, g_h0);
    cudaGetSymbolAddress(&p_h1, g_h1);
    cudaGetSymbolAddress(&p_xt, g_xt);
    cudaGetSymbolAddress(&p_hseq, g_hseq);
    cudaGetSymbolAddress(&p_xw0all, g_xw0all);
    cudaGetSymbolAddress(&p_p0all, g_p0all);
    cudaGetSymbolAddress(&p_xw, g_xw);          // FIX: device symbol via API, not host shadow

    cudaMemsetAsync(p_deg, 0, Nn * sizeof(float), 0);
    cudaMemsetAsync(p_cnt, 0, Nn * sizeof(int), 0);
    cudaMemsetAsync(p_cur, 0, Nn * sizeof(int), 0);
    cudaMemsetAsync(p_h0, 0, (size_t)Nn * Hh * sizeof(float), 0);
    cudaMemsetAsync(p_h1, 0, (size_t)Nn * Hh * sizeof(float), 0);

    k_transpose<<<(Nn * Ff * Tt + 255) / 256, 256>>>(x);
    k_trW<<<(192 * Hh + 255) / 256, 256>>>(ipw, opw);
    k_deg_hist<<<(Ee + 255) / 256, 256>>>(ei, ea);
    k_dinv<<<(Nn + 255) / 256, 256>>>();
    k_norm<<<(Ee + 255) / 256, 256>>>(ei, ea);
    k_scan<<<1, 1024>>>();
    k_fill<<<(Ee + 255) / 256, 256>>>(ei);

    // big hoisted precomputes
    k_gemm_xw<<<TN / 64, 256>>>((const float*)p_xt, Ff, TN, Wg0, (float*)p_xw0all);
    k_agg_all<<<(TN + 7) / 8, 256>>>(bg0);
    dim3 preg(TN / 64, 3);
    k_pre0<<<preg, 256>>>(Wu0, bu0, Wr0, br0, Wc0, bc0);

    const int GB = (Nn + 63) / 64;
    const int AGG_GRID = (Nn + 7) / 8;
    float* h0 = (float*)p_h0;
    float* h1 = (float*)p_h1;

    for (int t = 0; t < Tt; t++) {
        // layer0: fused urc (xi,g parts precomputed)
        k_urc0<<<GB, 256>>>(Wu0 + 96 * Hh, Wr0 + 96 * Hh, Wc0 + 96 * Hh,
                            (const float*)p_p0all + (size_t)t * Nn * 192, h0);
        // layer1
        k_gemm_xw<<<GB, 256>>>(h0, Hh, Nn, Wg1, (float*)p_xw);
        k_gcn_agg<<<AGG_GRID, 256>>>(bg1);
        k_urc1<<<GB, 256>>>(h0, Wu1, bu1, Wr1, br1, Wc1, bc1, h1,
                            (float*)p_hseq + (size_t)t * Nn * Hh);
    }

    k_attn<<<Nn, 32>>>(ipb, opb, ow, ob, out);
}